// round 17
// baseline (speedup 1.0000x reference)
#include <cuda_runtime.h>
#include <math.h>

#define BATCH   64
#define NLIST   512
#define THREADS 1024           // 2 threads per i-element
#define NBLK    128            // 2 CTAs per row = 1 cluster per row
#define TOPN    50
#define JSLOTS  52             // padded top slots (2 NaN dummies)

#define LOG_EPS (-23.025850929940457f)
#define LN2F    0.6931471805599453f

// 1/log1p(k) for k=0..52 (k=0 unused)
__constant__ float C_IL[53] = {
    0.0f,        1.44269504f, 0.91023923f, 0.72134752f, 0.62133493f,
    0.55811063f, 0.51389834f, 0.48089835f, 0.45511961f, 0.43429448f,
    0.41703239f, 0.40242960f, 0.38987124f, 0.37892269f, 0.36926938f,
    0.36067376f, 0.35295525f, 0.34597526f, 0.33962297f, 0.33380821f,
    0.32845724f, 0.32351538f, 0.31892891f, 0.31465802f, 0.31066747f,
    0.30692762f, 0.30341308f, 0.30010212f, 0.29697521f, 0.29401538f,
    0.29120814f, 0.28853901f, 0.28599983f, 0.28357871f, 0.28126653f,
    0.27905531f, 0.27693789f, 0.27490773f, 0.27295812f, 0.27108450f,
    0.26928330f, 0.26754748f, 0.26587369f, 0.26425870f, 0.26269878f,
    0.26119069f, 0.25973142f, 0.25831873f, 0.25694924f, 0.25562222f,
    0.25433417f, 0.25308478f, 0.25187249f
};

__device__ float        g_partial[NBLK];
__device__ unsigned int g_count = 0;

__global__ __launch_bounds__(THREADS, 1) __cluster_dims__(2, 1, 1)
void rank_loss_main(const float* __restrict__ logits,
                    const float* __restrict__ labels,
                    float* __restrict__ out) {
    __shared__ float  s_sl[NLIST];        // masked logits
    __shared__ float2 s_EG[NLIST];        // {Ei (NaN invalid), Gi} per element
    __shared__ int    s_cnt[THREADS];     // partial rank counts (4/element)
    __shared__ __align__(4) unsigned char sC[NLIST];  // capped ranks (cluster-shared)
    __shared__ float  s_rel[103 * 32];    // symmetric replicated: [d*32+lane]
    __shared__ float4 s_J[JSLOTS];        // top payloads {G, E(NaN dummy), h, qd}
    __shared__ float  s_iw[64];
    __shared__ float  s_idcg;
    __shared__ float  s_red[32];
    __shared__ bool   s_last;

    const int tid  = threadIdx.x;
    const int lane = tid & 31;
    const int b    = blockIdx.x >> 1;
    const int h    = blockIdx.x & 1;      // == cluster ctarank

    // --- issue input LDGs FIRST (DRAM latency overlaps LUT fill) ---
    float gr = 0.0f, lr = -1e9f;
    if (tid < NLIST) {
        gr = logits[b * NLIST + tid];
        lr = labels[b * NLIST + tid];
    }

    // --- symmetric replicated rel LUT from constant literals ---
    for (int idx = tid; idx < 103 * 32; idx += THREADS) {
        const int d = idx >> 5;
        const int k = abs(d - 51);
        s_rel[idx] = k ? 0.75f * fabsf(C_IL[k] - C_IL[k + 1]) : 0.0f;
    }

    // dummy top slots: E=NaN masks every pair; qd value irrelevant (masked)
    const float qnan = __int_as_float(0x7fffffff);
    if (tid < JSLOTS) s_J[tid] = make_float4(1.0f, qnan, 0.0f, 0.0f);

    // --- per-element precompute (threads 0..511 own one element each) ---
    float Gi_own = 0.0f, Ei_own = 0.0f, hi_own = 0.0f;
    if (tid < NLIST) {
        const bool  valid = lr > -1000.0f;
        const float lab   = valid ? lr : 0.0f;
        const float g     = valid ? gr : LOG_EPS;
        s_sl[tid] = g;
        if (tid < 64) s_iw[tid] = (tid < TOPN && valid) ? C_IL[tid + 1] : 0.0f;
        Gi_own = __expf(0.5f * g);
        Ei_own = valid ? __expf(0.5f * lab) : qnan;   // NaN -> pairs inactive
        hi_own = 0.5f * g;
        s_EG[tid] = make_float2(Ei_own, Gi_own);
    }
    __syncthreads();

    // --- warp 0: cooperative IDCG (overlaps with rank scan) ---
    if (tid < 32) {
        float v = s_iw[lane] + s_iw[lane + 32];
        #pragma unroll
        for (int o = 16; o; o >>= 1) v += __shfl_down_sync(0xffffffffu, v, o);
        if (lane == 0) s_idcg = (v > 0.0f) ? (1.0f / v) : 0.0f;
    }

    // --- rank scan, 4-way split: CTA ranks its 256 elements, 4 threads/element ---
    const int   el = (h << 8) + (tid & 255);
    const int   jq = tid >> 8;             // 0..3
    const float ge = s_sl[el];
    int c0 = 0, c1 = 0, c2 = 0, c3 = 0;
    const float4* p4 = (const float4*)(s_sl + (jq << 7));
    #pragma unroll 8
    for (int k = 0; k < 32; ++k) {
        float4 v = p4[k];                  // uniform addr -> broadcast
        c0 += (v.x > ge);
        c1 += (v.y > ge);
        c2 += (v.z > ge);
        c3 += (v.w > ge);
    }
    s_cnt[tid] = c0 + c1 + c2 + c3;
    __syncthreads();

    if (tid < 256) {
        const int cnt = s_cnt[tid] + s_cnt[tid + 256] + s_cnt[tid + 512] + s_cnt[tid + 768];
        // ties only among the invalid cluster (all at LOG_EPS): capped=51 either
        // way and such elements appear only in masked pairs -> plain '>' exact
        sC[el] = (unsigned char)min(cnt + 1, 51);
    }
    __syncthreads();

    // --- own-half scatter EARLY (capped known locally) + DSMEM push ---
    if (tid < NLIST && (tid >> 8) == h) {
        const int cap = sC[tid];
        if (cap <= TOPN)
            s_J[cap - 1] = make_float4(Gi_own, Ei_own, hi_own, 0.25f * C_IL[cap]);
    }
    if (tid < 64) {
        const int off = (h << 8) + (tid << 2);
        const unsigned w32   = *(const unsigned*)&sC[off];
        const unsigned laddr = (unsigned)__cvta_generic_to_shared(&sC[off]);
        unsigned paddr;
        asm("mapa.shared::cluster.u32 %0, %1, %2;"
            : "=r"(paddr) : "r"(laddr), "r"(h ^ 1));
        asm volatile("st.shared::cluster.u32 [%0], %1;"
                     :: "r"(paddr), "r"(w32) : "memory");
    }
    asm volatile("barrier.cluster.arrive.aligned;" ::: "memory");
    asm volatile("barrier.cluster.wait.aligned;" ::: "memory");

    // --- other-half scatter (capped now available from peer) ---
    if (tid < NLIST && (tid >> 8) != h) {
        const int cap = sC[tid];
        if (cap <= TOPN)
            s_J[cap - 1] = make_float4(Gi_own, Ei_own, hi_own, 0.25f * C_IL[cap]);
    }
    __syncthreads();

    // --- sparse pair phase: 2 threads/element, 13 slots each.
    //     Slot index s implies cj = s+1 (rank is a perfect hash) -> rel LUT
    //     address is base + immediate offset; qdj stored unpacked in s_J.w.
    //     Only pairs with a top-50 member have w != 0. (x,t) once; top-top
    //     twice across row -> 0.5x; i==j auto-masked (|Ei-Ej|=0).
    //     bce = ln2*lg2(Gi+Gj) - hi + dh*Ej/(Ei+Ej)  (orientation-free, exact)
    //     mask |Ei-Ej|>0: ordered '>' false on NaN -> invalid deactivates ---
    const int    i     = tid & 511;
    const int    sub   = tid >> 9;
    const float2 EG    = s_EG[i];          // LDS.64 (no global reload)
    const float  Ei    = EG.x, Gi = EG.y;
    const float  hi    = 0.5f * s_sl[i];
    const float  nhi   = -hi;
    const int    capped = sC[i];
    const float  qdi   = (capped <= TOPN) ? 0.25f * C_IL[capped] : 0.0f;

    const int    jbase = h * 26 + sub * 13;           // first slot, cj = jbase+1
    const float4* pJ   = s_J + jbase;
    const float* p_rel = s_rel + ((capped + 51 - (jbase + 1)) << 5) + lane;

    auto body = [&](const float4 A, const float relv, float& acc) {
        const float t2  = __fdividef(A.y, Ei + A.y);
        const float lg  = __log2f(Gi + A.x);
        const float dh  = hi - A.z;
        const float bce = fmaf(dh, t2, fmaf(lg, LN2F, nhi));
        const float w   = relv + fabsf(qdi - A.w);
        const float de  = Ei - A.y;                    // NaN if either invalid
        if (fabsf(de) > 0.0f) acc = fmaf(bce, w, acc); // predicated FFMA; NaN-safe
    };

    float a0 = 0.0f, a1 = 0.0f, a2 = 0.0f, a3 = 0.0f;
    #pragma unroll
    for (int oo = 0; oo < 12; oo += 4) {   // immediate rel offsets after unroll
        body(pJ[oo],     p_rel[-((oo)     << 5)], a0);
        body(pJ[oo + 1], p_rel[-((oo + 1) << 5)], a1);
        body(pJ[oo + 2], p_rel[-((oo + 2) << 5)], a2);
        body(pJ[oo + 3], p_rel[-((oo + 3) << 5)], a3);
    }
    body(pJ[12], p_rel[-(12 << 5)], a0);
    float acc = (a0 + a1) + (a2 + a3);
    if (capped <= TOPN) acc *= 0.5f;       // top-top pairs double-visited

    // --- deterministic block reduce (32 warps) + fused final reduce ---
    #pragma unroll
    for (int o = 16; o; o >>= 1) acc += __shfl_down_sync(0xffffffffu, acc, o);
    if (lane == 0) s_red[tid >> 5] = acc;
    __syncthreads();
    if (tid < 32) {
        float v = s_red[lane];
        #pragma unroll
        for (int o = 16; o; o >>= 1) v += __shfl_down_sync(0xffffffffu, v, o);
        if (lane == 0) {
            g_partial[blockIdx.x] = v * s_idcg * (1.0f / (float)BATCH);
            __threadfence();
            unsigned int old = atomicInc(&g_count, NBLK - 1);  // wraps -> replay-safe
            s_last = (old == NBLK - 1);
        }
    }
    __syncthreads();

    if (s_last) {
        __threadfence();
        if (tid < NBLK) {
            float v = ((volatile float*)g_partial)[tid];
            #pragma unroll
            for (int o = 16; o; o >>= 1) v += __shfl_down_sync(0xffffffffu, v, o);
            if (lane == 0) s_red[tid >> 5] = v;
        }
        __syncthreads();
        if (tid == 0) {
            float tot = 0.0f;
            #pragma unroll
            for (int w2 = 0; w2 < NBLK / 32; ++w2) tot += s_red[w2];
            out[0] = tot;
        }
    }
}

extern "C" void kernel_launch(void* const* d_in, const int* in_sizes, int n_in,
                              void* d_out, int out_size) {
    const float* logits = (const float*)d_in[0];
    const float* labels = (const float*)d_in[1];
    float* out = (float*)d_out;
    (void)in_sizes; (void)n_in; (void)out_size;

    rank_loss_main<<<NBLK, THREADS>>>(logits, labels, out);
}